// round 7
// baseline (speedup 1.0000x reference)
#include <cuda_runtime.h>

typedef unsigned long long ull;
typedef unsigned int u32;

#define NPOS   21824
#define BATCH  8
#define KTOP   1000
#define NCLS   80
#define CAND_MAX 4096

// Scratch (no allocation allowed -> __device__ globals)
__device__ ull    g_keys[BATCH * NPOS];
__device__ float4 g_boxes[BATCH * NPOS];
__device__ float  g_kind[BATCH * NPOS];

// per-image selected top-1024 (SoA)
__device__ float4 g_top_box[BATCH * 1024];
__device__ float  g_top_kind[BATCH * 1024];
__device__ float  g_top_score[BATCH * 1024];
__device__ float  g_top_area[BATCH * 1024];
// suppression bit-matrix: [b][i][w], bit j-of-word => i suppresses j=w*32+bit
__device__ u32    g_mask[BATCH * 1024 * 32];

__constant__ int   c_off[5]    = {0, 16384, 20480, 21504, 21760};
__constant__ int   c_logw[5]   = {7, 6, 5, 4, 3};
__constant__ float c_stride[5] = {8.f, 16.f, 32.f, 64.f, 128.f};

struct Ptrs { const float* cls[5]; const float* reg[5]; };

// ---------------------------------------------------------------------------
// Kernel 1: decode all levels -> per-position (key, box, kind)
// key = (float_bits(score) << 32) | (0xFFFFFFFF - pos)
// ---------------------------------------------------------------------------
__global__ void decode_kernel(Ptrs p) {
    int gid = blockIdx.x * blockDim.x + threadIdx.x;
    if (gid >= BATCH * NPOS) return;
    int b   = gid / NPOS;
    int pos = gid - b * NPOS;

    int lev = 0;
    if      (pos >= c_off[4]) lev = 4;
    else if (pos >= c_off[3]) lev = 3;
    else if (pos >= c_off[2]) lev = 2;
    else if (pos >= c_off[1]) lev = 1;

    int local = pos - c_off[lev];
    int lw = c_logw[lev];
    int w  = 1 << lw;
    int hw = w * w;
    int y  = local >> lw;
    int x  = local & (w - 1);

    const float* __restrict__ cbase = p.cls[lev] + (size_t)b * NCLS * hw + local;
    float best = cbase[0];
    int   bi   = 0;
    #pragma unroll 16
    for (int c = 1; c < NCLS; c++) {
        float v = cbase[(size_t)c * hw];
        if (v > best) { best = v; bi = c; }
    }
    float score = (best > 0.05f) ? best : 0.0f;

    const float* __restrict__ rbase = p.reg[lev] + (size_t)b * 4 * hw + local;
    float s  = c_stride[lev];
    float r0 = rbase[0]      * s;
    float r1 = rbase[hw]     * s;
    float r2 = rbase[2 * hw] * s;
    float r3 = rbase[3 * hw] * s;
    float cx = ((float)x + 0.5f) * s;
    float cy = ((float)y + 0.5f) * s;

    g_boxes[gid] = make_float4(cx - r0, cy - r1, cx + r2, cy + r3);
    g_kind[gid]  = (float)bi;
    g_keys[gid]  = (((ull)__float_as_uint(score)) << 32) |
                   (ull)(0xFFFFFFFFu - (u32)pos);
}

// ---------------------------------------------------------------------------
// Kernel 2: per-image select top-1000 (exact radix select; pass-1 fused with
//           staging; winners+candidates compaction so the final compact scans
//           only ~hundreds), bitonic sort 1024, gather SoA.
// ---------------------------------------------------------------------------
#define SEL_SMEM ((NPOS + 1024 + CAND_MAX) * 8)   // 215552 bytes

__global__ void __launch_bounds__(1024, 1) select_kernel() {
    extern __shared__ ull sm[];
    ull* s_keys = sm;                    // NPOS
    ull* s_top  = sm + NPOS;             // 1024
    ull* s_cand = sm + NPOS + 1024;      // CAND_MAX

    __shared__ u32 s_hist[256];
    __shared__ int s_cnt, s_wcnt, s_digit, s_rem, s_match;

    int tid  = threadIdx.x;
    int lane = tid & 31;
    int b    = blockIdx.x;
    const ull* __restrict__ gk = g_keys + (size_t)b * NPOS;

    if (tid < 256) s_hist[tid] = 0;
    s_top[tid] = 0;                      // winners land here later; rest padding
    __syncthreads();

    // ---- fused stage + pass-1 (shift=56) histogram ----
    for (int i = tid; i < NPOS; i += 1024) {
        ull k = gk[i];
        s_keys[i] = k;
        u32 d      = (u32)(k >> 56);
        u32 act    = __activemask();
        u32 peers  = __match_any_sync(act, d);
        int leader = __ffs(peers) - 1;
        if (lane == leader) atomicAdd(&s_hist[d], (u32)__popc(peers));
    }
    __syncthreads();

    ull prefix    = 0;
    int remaining = KTOP;
    bool list = false;
    int listn = 0, nw = 0;

    for (int shift = 56; shift >= 0; shift -= 8) {
        if (shift != 56) {
            if (tid < 256) s_hist[tid] = 0;
            __syncthreads();
            ull himask = ~0ull << (shift + 8);
            const ull* src = list ? s_cand : s_keys;
            int n = list ? listn : NPOS;
            for (int i = tid; i < n; i += 1024) {
                ull k = src[i];
                if ((k & himask) == prefix) {
                    u32 d      = (u32)(k >> shift) & 255u;
                    u32 act    = __activemask();
                    u32 peers  = __match_any_sync(act, d);
                    int leader = __ffs(peers) - 1;
                    if (lane == leader) atomicAdd(&s_hist[d], (u32)__popc(peers));
                }
            }
            __syncthreads();
        }

        // ---- warp-0 parallel suffix scan of the 256-bin histogram ----
        if (tid < 32) {
            u32 h[8], suf[8];
            #pragma unroll
            for (int q = 0; q < 8; q++) h[q] = s_hist[tid * 8 + q];
            u32 run = 0;
            #pragma unroll
            for (int q = 7; q >= 0; q--) { run += h[q]; suf[q] = run; }
            u32 x = run;
            #pragma unroll
            for (int off = 1; off < 32; off <<= 1) {
                u32 y = __shfl_down_sync(0xffffffffu, x, off);
                if (lane + off < 32) x += y;
            }
            u32 excl = x - run;   // totals of lanes > me
            #pragma unroll
            for (int q = 0; q < 8; q++) s_hist[tid * 8 + q] = suf[q] + excl;
        }
        __syncthreads();
        if (tid < 256) {
            u32 suf  = s_hist[tid];
            u32 sufn = (tid == 255) ? 0u : s_hist[tid + 1];
            if (suf >= (u32)remaining && sufn < (u32)remaining) {
                s_digit = tid;
                s_rem   = remaining - (int)sufn;
                s_match = (int)(suf - sufn);
            }
        }
        __syncthreads();

        prefix |= ((ull)(u32)s_digit) << shift;
        remaining = s_rem;
        int matchcnt = s_match;

        // ---- one-time compaction: winners -> s_top, boundary bin -> s_cand ----
        if (!list && matchcnt <= CAND_MAX && shift > 0) {
            ull pmask = ~0ull << shift;
            if (tid == 0) { s_cnt = 0; s_wcnt = 0; }
            __syncthreads();
            for (int i = tid; i < NPOS; i += 1024) {
                ull k  = s_keys[i];
                ull kp = k & pmask;
                if (kp == prefix) {
                    u32 act    = __activemask();
                    u32 lt     = act & ((1u << lane) - 1u);
                    int rank   = __popc(lt);
                    int leader = __ffs(act) - 1;
                    int base   = 0;
                    if (lane == leader) base = atomicAdd(&s_cnt, __popc(act));
                    base = __shfl_sync(act, base, leader);
                    s_cand[base + rank] = k;
                } else if (kp > prefix) {
                    u32 act    = __activemask();
                    u32 lt     = act & ((1u << lane) - 1u);
                    int rank   = __popc(lt);
                    int leader = __ffs(act) - 1;
                    int base   = 0;
                    if (lane == leader) base = atomicAdd(&s_wcnt, __popc(act));
                    base = __shfl_sync(act, base, leader);
                    s_top[base + rank] = k;   // definite winner
                }
            }
            __syncthreads();
            list  = true;
            listn = matchcnt;
            nw    = s_wcnt;
        }
    }
    // prefix == exact KTOP-th largest key

    // ---- final fill: append cands (or full scan fallback) with k >= prefix ----
    if (tid == 0) s_cnt = nw;
    __syncthreads();
    {
        const ull* src = list ? s_cand : s_keys;
        int n = list ? listn : NPOS;
        for (int i = tid; i < n; i += 1024) {
            ull k = src[i];
            if (k >= prefix) {
                u32 act    = __activemask();
                u32 lt     = act & ((1u << lane) - 1u);
                int rank   = __popc(lt);
                int leader = __ffs(act) - 1;
                int base   = 0;
                if (lane == leader) base = atomicAdd(&s_cnt, __popc(act));
                base = __shfl_sync(act, base, leader);
                s_top[base + rank] = k;
            }
        }
    }

    // ---- bitonic sort 1024, descending ----
    for (int k2 = 2; k2 <= 1024; k2 <<= 1) {
        for (int j = k2 >> 1; j > 0; j >>= 1) {
            __syncthreads();
            int ixj = tid ^ j;
            if (ixj > tid) {
                ull a = s_top[tid], c = s_top[ixj];
                bool desc = ((tid & k2) == 0);
                if (desc ? (a < c) : (a > c)) { s_top[tid] = c; s_top[ixj] = a; }
            }
        }
    }
    __syncthreads();

    // ---- gather into global SoA ----
    {
        ull k    = s_top[tid];
        float sc = __uint_as_float((u32)(k >> 32));
        u32 idx  = 0xFFFFFFFFu - (u32)(k & 0xFFFFFFFFull);
        float4 bx = make_float4(0.f, 0.f, 0.f, 0.f);
        float  kd = 0.f;
        if (tid < KTOP) {
            bx = g_boxes[(size_t)b * NPOS + idx];
            kd = g_kind[(size_t)b * NPOS + idx];
        }
        int o = b * 1024 + tid;
        g_top_box[o]   = bx;
        g_top_kind[o]  = kd;
        g_top_score[o] = sc;
        g_top_area[o]  = fmaxf(bx.z - bx.x, 0.f) * fmaxf(bx.w - bx.y, 0.f);
    }
}

// ---------------------------------------------------------------------------
// Kernel 3: suppression bit-matrix, spread across chip.
// Division-free IoU test: inter > 0.5*denom  <=>  iou > 0.5 (denom > 0).
// ---------------------------------------------------------------------------
__global__ void __launch_bounds__(256) mask_kernel() {
    __shared__ float s_x1[1024], s_y1[1024], s_x2[1024], s_y2[1024];
    __shared__ float s_area[1024], s_kind[1024];

    int tid = threadIdx.x;
    int b   = blockIdx.y;
    int r0  = blockIdx.x * 64;

    for (int t = tid; t < 1024; t += 256) {
        float4 bx = g_top_box[b * 1024 + t];
        s_x1[t] = bx.x; s_y1[t] = bx.y; s_x2[t] = bx.z; s_y2[t] = bx.w;
        s_area[t] = g_top_area[b * 1024 + t];
        s_kind[t] = g_top_kind[b * 1024 + t];
    }
    __syncthreads();

    int w  = tid & 31;
    int wi = tid >> 5;
    int jbase = w * 32;

    for (int k = 0; k < 8; k++) {
        int i = r0 + wi * 8 + k;
        u32 m = 0;
        if (i < KTOP && (jbase + 31) > i) {
            float bx1 = s_x1[i], by1 = s_y1[i], bx2 = s_x2[i], by2 = s_y2[i];
            float ai = s_area[i], ki = s_kind[i];
            #pragma unroll
            for (int it = 0; it < 32; it++) {
                int jr = (it + w) & 31;       // rotate -> conflict-free banks
                int j  = jbase + jr;
                if (j > i && j < KTOP && s_kind[j] == ki) {
                    float xx1 = fmaxf(bx1, s_x1[j]);
                    float yy1 = fmaxf(by1, s_y1[j]);
                    float xx2 = fminf(bx2, s_x2[j]);
                    float yy2 = fminf(by2, s_y2[j]);
                    float inter = fmaxf(xx2 - xx1, 0.f) * fmaxf(yy2 - yy1, 0.f);
                    float denom = ai + s_area[j] - inter + 1e-9f;
                    if (inter > 0.5f * denom) m |= (1u << jr);
                }
            }
        }
        g_mask[((size_t)b * 1024 + i) * 32 + w] = m;
    }
}

// ---------------------------------------------------------------------------
// Kernel 4: sweep from SHARED mask + output. grid=BATCH, 256 threads
// (<=255 regs/thread -> per-chunk register arrays do NOT spill to local).
// ---------------------------------------------------------------------------
#define SWEEP_SMEM (1024 * 32 * 4)   // 131072 bytes

__global__ void __launch_bounds__(256, 1) sweep_out_kernel(float* __restrict__ out) {
    extern __shared__ u32 s_mask[];
    __shared__ u32 s_remw[32];
    int tid  = threadIdx.x;
    int lane = tid & 31;
    int b    = blockIdx.x;

    // stage 128KB mask into shared (coalesced uint4, 32 per thread)
    const uint4* __restrict__ M4 = (const uint4*)(g_mask + (size_t)b * 1024 * 32);
    uint4* S4 = (uint4*)s_mask;
    #pragma unroll 4
    for (int i = tid; i < 1024 * 32 / 4; i += 256) S4[i] = M4[i];
    __syncthreads();

    if (tid < 32) {
        u32 rem = 0;
        for (int c = 0; c < 32; c++) {
            u32 mk[32], mc[32];
            #pragma unroll
            for (int k = 0; k < 32; k++) {
                int i = c * 32 + k;
                mk[k] = s_mask[i * 32 + lane];   // bank = lane (conflict-free)
                mc[k] = s_mask[i * 32 + c];      // broadcast
            }
            u32 cur = __shfl_sync(0xffffffffu, rem, c);
            u32 acc = 0;
            #pragma unroll
            for (int k = 0; k < 32; k++) {
                if (!((cur >> k) & 1u)) { acc |= mk[k]; cur |= mc[k]; }
            }
            rem |= acc;
        }
        s_remw[lane] = rem;
    }
    __syncthreads();

    for (int t = tid; t < KTOP; t += 256) {
        bool removed = (s_remw[t >> 5] >> (t & 31)) & 1u;
        int o = b * 1024 + t;
        float sc = g_top_score[o];
        float out_sc = (!removed && sc > 0.0f) ? sc : 0.0f;
        float4 bx = g_top_box[o];
        float* op = out + ((size_t)b * KTOP + t) * 6;
        op[0] = bx.x; op[1] = bx.y; op[2] = bx.z; op[3] = bx.w;
        op[4] = g_top_kind[o];
        op[5] = out_sc;
    }
}

// ---------------------------------------------------------------------------
extern "C" void kernel_launch(void* const* d_in, const int* in_sizes, int n_in,
                              void* d_out, int out_size) {
    bool dict_order = (in_sizes[1] != 2621440);
    Ptrs p;
    for (int i = 0; i < 5; i++) {
        if (dict_order) {
            p.cls[i] = (const float*)d_in[3 * i];
            p.reg[i] = (const float*)d_in[3 * i + 2];
        } else {
            p.cls[i] = (const float*)d_in[i];
            p.reg[i] = (const float*)d_in[10 + i];
        }
    }

    int total = BATCH * NPOS;
    decode_kernel<<<(total + 255) / 256, 256>>>(p);

    cudaFuncSetAttribute(select_kernel,
                         cudaFuncAttributeMaxDynamicSharedMemorySize, SEL_SMEM);
    select_kernel<<<BATCH, 1024, SEL_SMEM>>>();

    mask_kernel<<<dim3(16, BATCH), 256>>>();

    cudaFuncSetAttribute(sweep_out_kernel,
                         cudaFuncAttributeMaxDynamicSharedMemorySize, SWEEP_SMEM);
    sweep_out_kernel<<<BATCH, 256, SWEEP_SMEM>>>((float*)d_out);
}

// round 8
// speedup vs baseline: 1.3444x; 1.3444x over previous
#include <cuda_runtime.h>

typedef unsigned long long ull;
typedef unsigned int u32;

#define NPOS   21824
#define BATCH  8
#define KTOP   1000
#define NCLS   80
#define CAND_MAX 4096
#define FULLM  0xffffffffu

// Scratch (no allocation allowed -> __device__ globals)
__device__ ull    g_keys[BATCH * NPOS];
__device__ float4 g_boxes[BATCH * NPOS];
__device__ float  g_kind[BATCH * NPOS];

__constant__ int   c_off[5]    = {0, 16384, 20480, 21504, 21760};
__constant__ int   c_logw[5]   = {7, 6, 5, 4, 3};
__constant__ float c_stride[5] = {8.f, 16.f, 32.f, 64.f, 128.f};

struct Ptrs { const float* cls[5]; const float* reg[5]; };

// ---------------------------------------------------------------------------
// Kernel 1: decode all levels -> per-position (key, box, kind)
// key = (float_bits(score) << 32) | (0xFFFFFFFF - pos)
// ---------------------------------------------------------------------------
__global__ void decode_kernel(Ptrs p) {
    int gid = blockIdx.x * blockDim.x + threadIdx.x;
    if (gid >= BATCH * NPOS) return;
    int b   = gid / NPOS;
    int pos = gid - b * NPOS;

    int lev = 0;
    if      (pos >= c_off[4]) lev = 4;
    else if (pos >= c_off[3]) lev = 3;
    else if (pos >= c_off[2]) lev = 2;
    else if (pos >= c_off[1]) lev = 1;

    int local = pos - c_off[lev];
    int lw = c_logw[lev];
    int w  = 1 << lw;
    int hw = w * w;
    int y  = local >> lw;
    int x  = local & (w - 1);

    const float* __restrict__ cbase = p.cls[lev] + (size_t)b * NCLS * hw + local;
    float best = cbase[0];
    int   bi   = 0;
    #pragma unroll 16
    for (int c = 1; c < NCLS; c++) {
        float v = cbase[(size_t)c * hw];
        if (v > best) { best = v; bi = c; }
    }
    float score = (best > 0.05f) ? best : 0.0f;

    const float* __restrict__ rbase = p.reg[lev] + (size_t)b * 4 * hw + local;
    float s  = c_stride[lev];
    float r0 = rbase[0]      * s;
    float r1 = rbase[hw]     * s;
    float r2 = rbase[2 * hw] * s;
    float r3 = rbase[3 * hw] * s;
    float cx = ((float)x + 0.5f) * s;
    float cy = ((float)y + 0.5f) * s;

    g_boxes[gid] = make_float4(cx - r0, cy - r1, cx + r2, cy + r3);
    g_kind[gid]  = (float)bi;
    g_keys[gid]  = (((ull)__float_as_uint(score)) << 32) |
                   (ull)(0xFFFFFFFFu - (u32)pos);
}

// ---------------------------------------------------------------------------
// Kernel 2 (FUSED): per-image block does
//   radix select top-1000 -> bitonic sort -> gather boxes ->
//   class-bucketed sparse NMS mask (smem, overlays dead key region) ->
//   sparsity-aware serial sweep -> output.
// ---------------------------------------------------------------------------
#define SEL_SMEM ((NPOS + 1024 + CAND_MAX) * 8)   // 215552 bytes dynamic

// overlay offsets (inside the dead s_keys region, 174592 bytes)
#define OV_MASK   0         // u32[1024*32]  131072
#define OV_DIAG   131072    // u32[1024]       4096
#define OV_X1     135168
#define OV_Y1     139264
#define OV_X2     143360
#define OV_Y2     147456
#define OV_AREA   151552
#define OV_KIND   155648    // int[1024]
#define OV_LIST   159744    // u32[1024]
#define OV_ROWOR  163840    // u32[1024]      -> ends 167936 < 174592

__global__ void __launch_bounds__(1024, 1) fused_kernel(float* __restrict__ out) {
    extern __shared__ char smc[];
    ull* s_keys = (ull*)smc;                         // phase A
    ull* s_top  = (ull*)(smc + NPOS * 8);            // persists
    ull* s_cand = (ull*)(smc + (NPOS + 1024) * 8);   // phase A

    __shared__ u32 s_hist[2][256];
    __shared__ int s_cnt, s_wcnt, s_digit, s_rem, s_match;
    __shared__ u32 s_ccnt[96], s_coff[96], s_cwr[96];
    __shared__ u32 s_remw[32];

    int tid  = threadIdx.x;
    int lane = tid & 31;
    int hslot = (tid >> 5) & 1;
    int b    = blockIdx.x;
    const ull* __restrict__ gk = g_keys + (size_t)b * NPOS;

    if (tid < 256) { s_hist[0][tid] = 0; s_hist[1][tid] = 0; }
    s_top[tid] = 0;
    __syncthreads();

    // ---- fused stage + pass-1 (shift=56) histogram ----
    #pragma unroll 2
    for (int i = tid; i < NPOS; i += 1024) {
        ull k = gk[i];
        s_keys[i] = k;
        u32 d      = (u32)(k >> 56);
        u32 act    = __activemask();
        u32 peers  = __match_any_sync(act, d);
        int leader = __ffs(peers) - 1;
        if (lane == leader) atomicAdd(&s_hist[hslot][d], (u32)__popc(peers));
    }
    __syncthreads();

    ull prefix    = 0;
    int remaining = KTOP;
    bool list = false;
    int listn = 0, nw = 0;

    for (int shift = 56; shift >= 0; shift -= 8) {
        if (shift != 56) {
            if (tid < 256) { s_hist[0][tid] = 0; s_hist[1][tid] = 0; }
            __syncthreads();
            ull himask = ~0ull << (shift + 8);
            const ull* src = list ? s_cand : s_keys;
            int n = list ? listn : NPOS;
            for (int i = tid; i < n; i += 1024) {
                ull k = src[i];
                if ((k & himask) == prefix) {
                    u32 d      = (u32)(k >> shift) & 255u;
                    u32 act    = __activemask();
                    u32 peers  = __match_any_sync(act, d);
                    int leader = __ffs(peers) - 1;
                    if (lane == leader) atomicAdd(&s_hist[hslot][d], (u32)__popc(peers));
                }
            }
            __syncthreads();
        }

        // ---- warp-0 parallel suffix scan of the 256-bin histogram ----
        if (tid < 32) {
            u32 h[8], suf[8];
            #pragma unroll
            for (int q = 0; q < 8; q++)
                h[q] = s_hist[0][tid * 8 + q] + s_hist[1][tid * 8 + q];
            u32 run = 0;
            #pragma unroll
            for (int q = 7; q >= 0; q--) { run += h[q]; suf[q] = run; }
            u32 x = run;
            #pragma unroll
            for (int off = 1; off < 32; off <<= 1) {
                u32 y = __shfl_down_sync(FULLM, x, off);
                if (lane + off < 32) x += y;
            }
            u32 excl = x - run;
            #pragma unroll
            for (int q = 0; q < 8; q++) s_hist[0][tid * 8 + q] = suf[q] + excl;
        }
        __syncthreads();
        if (tid < 256) {
            u32 suf  = s_hist[0][tid];
            u32 sufn = (tid == 255) ? 0u : s_hist[0][tid + 1];
            if (suf >= (u32)remaining && sufn < (u32)remaining) {
                s_digit = tid;
                s_rem   = remaining - (int)sufn;
                s_match = (int)(suf - sufn);
            }
        }
        __syncthreads();

        prefix |= ((ull)(u32)s_digit) << shift;
        remaining = s_rem;
        int matchcnt = s_match;

        // ---- one-time compaction: winners -> s_top, boundary bin -> s_cand ----
        if (!list && matchcnt <= CAND_MAX && shift > 0) {
            ull pmask = ~0ull << shift;
            if (tid == 0) { s_cnt = 0; s_wcnt = 0; }
            __syncthreads();
            for (int i = tid; i < NPOS; i += 1024) {
                ull k  = s_keys[i];
                ull kp = k & pmask;
                if (kp == prefix) {
                    u32 act    = __activemask();
                    u32 lt     = act & ((1u << lane) - 1u);
                    int rank   = __popc(lt);
                    int leader = __ffs(act) - 1;
                    int base   = 0;
                    if (lane == leader) base = atomicAdd(&s_cnt, __popc(act));
                    base = __shfl_sync(act, base, leader);
                    s_cand[base + rank] = k;
                } else if (kp > prefix) {
                    u32 act    = __activemask();
                    u32 lt     = act & ((1u << lane) - 1u);
                    int rank   = __popc(lt);
                    int leader = __ffs(act) - 1;
                    int base   = 0;
                    if (lane == leader) base = atomicAdd(&s_wcnt, __popc(act));
                    base = __shfl_sync(act, base, leader);
                    s_top[base + rank] = k;   // definite winner
                }
            }
            __syncthreads();
            list  = true;
            listn = matchcnt;
            nw    = s_wcnt;
        }
    }
    // prefix == exact KTOP-th largest key

    // ---- final fill: append cands (or full scan fallback) with k >= prefix ----
    if (tid == 0) s_cnt = nw;
    __syncthreads();
    {
        const ull* src = list ? s_cand : s_keys;
        int n = list ? listn : NPOS;
        for (int i = tid; i < n; i += 1024) {
            ull k = src[i];
            if (k >= prefix) {
                u32 act    = __activemask();
                u32 lt     = act & ((1u << lane) - 1u);
                int rank   = __popc(lt);
                int leader = __ffs(act) - 1;
                int base   = 0;
                if (lane == leader) base = atomicAdd(&s_cnt, __popc(act));
                base = __shfl_sync(act, base, leader);
                s_top[base + rank] = k;
            }
        }
    }

    // ---- bitonic sort 1024, descending ----
    for (int k2 = 2; k2 <= 1024; k2 <<= 1) {
        for (int j = k2 >> 1; j > 0; j >>= 1) {
            __syncthreads();
            int ixj = tid ^ j;
            if (ixj > tid) {
                ull a = s_top[tid], c = s_top[ixj];
                bool desc = ((tid & k2) == 0);
                if (desc ? (a < c) : (a > c)) { s_top[tid] = c; s_top[ixj] = a; }
            }
        }
    }
    __syncthreads();
    // s_keys / s_cand are DEAD from here: overlay region becomes mask + SoA.

    u32*   s_mask  = (u32*)  (smc + OV_MASK);
    u32*   s_diag  = (u32*)  (smc + OV_DIAG);
    float* s_x1    = (float*)(smc + OV_X1);
    float* s_y1    = (float*)(smc + OV_Y1);
    float* s_x2    = (float*)(smc + OV_X2);
    float* s_y2    = (float*)(smc + OV_Y2);
    float* s_area  = (float*)(smc + OV_AREA);
    int*   s_kindi = (int*)  (smc + OV_KIND);
    u32*   s_list  = (u32*)  (smc + OV_LIST);
    u32*   s_rowor = (u32*)  (smc + OV_ROWOR);

    // zero mask (uint4) + class counters
    {
        uint4* m4 = (uint4*)s_mask;
        #pragma unroll
        for (int i = 0; i < 8; i++) m4[tid + i * 1024] = make_uint4(0, 0, 0, 0);
        if (tid < 96) s_ccnt[tid] = 0;
    }
    __syncthreads();

    // ---- gather boxes + count classes ----
    int myk = -1;
    {
        ull k    = s_top[tid];
        u32 idx  = 0xFFFFFFFFu - (u32)(k & 0xFFFFFFFFull);
        float4 bx = make_float4(0.f, 0.f, 0.f, 0.f);
        if (tid < KTOP) {
            bx = g_boxes[(size_t)b * NPOS + idx];
            myk = (int)g_kind[(size_t)b * NPOS + idx];
            atomicAdd(&s_ccnt[myk], 1u);
        }
        s_x1[tid] = bx.x; s_y1[tid] = bx.y; s_x2[tid] = bx.z; s_y2[tid] = bx.w;
        s_kindi[tid] = myk;
        s_area[tid] = fmaxf(bx.z - bx.x, 0.f) * fmaxf(bx.w - bx.y, 0.f);
    }
    __syncthreads();

    // ---- exclusive prefix over 80 (padded 96) class counts: warp 0 ----
    if (tid < 32) {
        int c0 = tid * 3;
        u32 a0 = s_ccnt[c0], a1 = s_ccnt[c0 + 1], a2 = s_ccnt[c0 + 2];
        u32 tot = a0 + a1 + a2;
        u32 x = tot;
        #pragma unroll
        for (int off = 1; off < 32; off <<= 1) {
            u32 y = __shfl_up_sync(FULLM, x, off);
            if (lane >= off) x += y;
        }
        u32 excl = x - tot;
        s_coff[c0]     = excl;           s_cwr[c0]     = excl;
        s_coff[c0 + 1] = excl + a0;      s_cwr[c0 + 1] = excl + a0;
        s_coff[c0 + 2] = excl + a0 + a1; s_cwr[c0 + 2] = excl + a0 + a1;
    }
    __syncthreads();

    // ---- scatter into class lists ----
    int myrank = 0;
    if (tid < KTOP) {
        myrank = (int)atomicAdd(&s_cwr[myk], 1u) - (int)s_coff[myk];
        s_list[s_coff[myk] + myrank] = (u32)tid;
    }
    __syncthreads();

    // ---- same-class pair compare -> sparse mask bits ----
    if (tid < KTOP) {
        int off = (int)s_coff[myk];
        int n   = (int)s_cwr[myk] - off;
        float bx1 = s_x1[tid], by1 = s_y1[tid], bx2 = s_x2[tid], by2 = s_y2[tid];
        float myar = s_area[tid];
        for (int r = myrank + 1; r < n; r++) {
            int o = (int)s_list[off + r];
            float xx1 = fmaxf(bx1, s_x1[o]);
            float yy1 = fmaxf(by1, s_y1[o]);
            float xx2 = fminf(bx2, s_x2[o]);
            float yy2 = fminf(by2, s_y2[o]);
            float inter = fmaxf(xx2 - xx1, 0.f) * fmaxf(yy2 - yy1, 0.f);
            int i = min(tid, o), j = max(tid, o);
            float denom = s_area[i] + s_area[j] - inter + 1e-9f;
            if (inter > 0.5f * denom)
                atomicOr(&s_mask[i * 32 + (j >> 5)], 1u << (j & 31));
        }
    }
    __syncthreads();

    // ---- diag + rowOR precompute ----
    {
        u32 ro = 0;
        #pragma unroll 8
        for (int w = 0; w < 32; w++) ro |= s_mask[tid * 32 + w];
        s_rowor[tid] = ro;
        s_diag[tid]  = s_mask[tid * 32 + (tid >> 5)];
    }
    __syncthreads();

    // ---- sparsity-aware serial sweep on warp 0 ----
    if (tid < 32) {
        u32 rem = 0;
        for (int c = 0; c < 32; c++) {
            u32 ro = s_rowor[c * 32 + lane];
            if (__reduce_or_sync(FULLM, ro) == 0u) continue;   // chunk has no edges
            u32 dg  = s_diag[c * 32 + lane];
            u32 dOR = __reduce_or_sync(FULLM, dg);
            u32 cur = __shfl_sync(FULLM, rem, c);
            if (dOR == 0u) {
                // fast path: no intra-chunk edges; kept = ~cur
                u32 K = ~cur;
                u32 a0 = 0, a1 = 0, a2 = 0, a3 = 0;
                #pragma unroll
                for (int k = 0; k < 32; k += 4) {
                    a0 |= s_mask[(c * 32 + k    ) * 32 + lane] & (u32)(((int)(K << (31 - k)))       >> 31);
                    a1 |= s_mask[(c * 32 + k + 1) * 32 + lane] & (u32)(((int)(K << (31 - (k + 1)))) >> 31);
                    a2 |= s_mask[(c * 32 + k + 2) * 32 + lane] & (u32)(((int)(K << (31 - (k + 2)))) >> 31);
                    a3 |= s_mask[(c * 32 + k + 3) * 32 + lane] & (u32)(((int)(K << (31 - (k + 3)))) >> 31);
                }
                rem |= (a0 | a1) | (a2 | a3);
            } else {
                // slow path (rare): serial chain with preloaded words
                u32 mk[32], mc[32];
                #pragma unroll
                for (int k = 0; k < 32; k++) {
                    mk[k] = s_mask[(c * 32 + k) * 32 + lane];
                    mc[k] = s_diag[c * 32 + k];
                }
                u32 acc = 0;
                #pragma unroll
                for (int k = 0; k < 32; k++) {
                    if (!((cur >> k) & 1u)) { acc |= mk[k]; cur |= mc[k]; }
                }
                rem |= acc;
            }
        }
        s_remw[lane] = rem;
    }
    __syncthreads();

    // ---- output ----
    if (tid < KTOP) {
        bool removed = (s_remw[tid >> 5] >> (tid & 31)) & 1u;
        float sc = __uint_as_float((u32)(s_top[tid] >> 32));
        float out_sc = (!removed && sc > 0.0f) ? sc : 0.0f;
        float* op = out + ((size_t)b * KTOP + tid) * 6;
        op[0] = s_x1[tid]; op[1] = s_y1[tid]; op[2] = s_x2[tid]; op[3] = s_y2[tid];
        op[4] = (float)s_kindi[tid];
        op[5] = out_sc;
    }
}

// ---------------------------------------------------------------------------
extern "C" void kernel_launch(void* const* d_in, const int* in_sizes, int n_in,
                              void* d_out, int out_size) {
    bool dict_order = (in_sizes[1] != 2621440);
    Ptrs p;
    for (int i = 0; i < 5; i++) {
        if (dict_order) {
            p.cls[i] = (const float*)d_in[3 * i];
            p.reg[i] = (const float*)d_in[3 * i + 2];
        } else {
            p.cls[i] = (const float*)d_in[i];
            p.reg[i] = (const float*)d_in[10 + i];
        }
    }

    int total = BATCH * NPOS;
    decode_kernel<<<(total + 255) / 256, 256>>>(p);

    cudaFuncSetAttribute(fused_kernel,
                         cudaFuncAttributeMaxDynamicSharedMemorySize, SEL_SMEM);
    fused_kernel<<<BATCH, 1024, SEL_SMEM>>>((float*)d_out);
}